// round 16
// baseline (speedup 1.0000x reference)
#include <cuda_runtime.h>
#include <cuda_fp16.h>
#include <cstdint>

#define BATCH 65536
#define NP 320

// proj GEMM: BM=64, BN=320, BK=64, 256 threads, 2 CTAs/SM (M-split), merged segs
#define PBM 64
#define PBK 64
#define SA_STR 72     // 64 + 8 pad (halves)
#define SB_STR 328    // 320 + 8 pad (halves)
#define PROJ_SMEM ((2*(PBM*SA_STR + PBK*SB_STR)) * 2)     // 102400 B

// attention kernel: one 128-row P tile + double-buffered A tiles, 256 threads
#define SP_STR 328
#define AA_STR 72
#define ATT_SMEM ((128*SP_STR + 2*NP*AA_STR) * 2 + 384*4) // 177664 B

__device__ __align__(16) __half g_Wt [768  * NP];   // [K][NP]
__device__ __align__(16) __half g_Wim[2048 * NP];
__device__ __align__(16) __half g_As [3 * NP * NP];   // sym lower-tri + u in row 300 (rest 0)
__device__ float g_C[3];
__device__ __align__(16) __half g_Ph[3][(size_t)BATCH * NP];

static __device__ __forceinline__ uint32_t su32(const void* p) {
    return (uint32_t)__cvta_generic_to_shared(p);
}
static __device__ __forceinline__ void cp16(const __half* dst, const __half* src) {
    asm volatile("cp.async.cg.shared.global [%0], [%1], 16;\n" :: "r"(su32(dst)), "l"(src));
}
static __device__ __forceinline__ void cpcommit() { asm volatile("cp.async.commit_group;\n"); }
static __device__ __forceinline__ void cpwait0()  { asm volatile("cp.async.wait_group 0;\n" ::: "memory"); }
static __device__ __forceinline__ void cpwait1()  { asm volatile("cp.async.wait_group 1;\n" ::: "memory"); }
static __device__ __forceinline__ void ldsm4(uint32_t* r, uint32_t a) {
    asm volatile("ldmatrix.sync.aligned.m8n8.x4.shared.b16 {%0,%1,%2,%3}, [%4];\n"
                 : "=r"(r[0]), "=r"(r[1]), "=r"(r[2]), "=r"(r[3]) : "r"(a));
}
static __device__ __forceinline__ void ldsm4t(uint32_t* r, uint32_t a) {
    asm volatile("ldmatrix.sync.aligned.m8n8.x4.trans.shared.b16 {%0,%1,%2,%3}, [%4];\n"
                 : "=r"(r[0]), "=r"(r[1]), "=r"(r[2]), "=r"(r[3]) : "r"(a));
}
static __device__ __forceinline__ void mma16816(float* c, const uint32_t* a, const uint32_t* b) {
    asm volatile("mma.sync.aligned.m16n8k16.row.col.f32.f16.f16.f32 "
                 "{%0,%1,%2,%3}, {%4,%5,%6,%7}, {%8,%9}, {%0,%1,%2,%3};\n"
                 : "+f"(c[0]), "+f"(c[1]), "+f"(c[2]), "+f"(c[3])
                 : "r"(a[0]), "r"(a[1]), "r"(a[2]), "r"(a[3]), "r"(b[0]), "r"(b[1]));
}

// ---- convert weight [K x 300] fp32 -> [K x NP] fp16 (zero-padded) ----
__global__ void k_convW(const float* __restrict__ src, int which, int K) {
    __half* dst = which ? g_Wim : g_Wt;
    int i = blockIdx.x * 256 + threadIdx.x;
    if (i < K * NP) {
        int k = i / NP, n = i - k * NP;
        dst[i] = __float2half_rn(n < 300 ? src[k * 300 + n] : 0.f);
    }
}

// ---- fused symmetrized-triangular prep: for lower-tri 32x32 block pair (bi>=bj)
// computes a_ij = Wq[i].Wk[j] and a_ji = Wq[j].Wk[i]; writes
// As[i][j] = a_ij + a_ji (i>j), As[i][i] = a_ii. Upper/padding stay zero-init. ----
__global__ void k_prepAs(const float* __restrict__ Wq0, const float* __restrict__ Wk0,
                         const float* __restrict__ Wq1, const float* __restrict__ Wk1,
                         const float* __restrict__ Wq2, const float* __restrict__ Wk2) {
    int b = blockIdx.z;
    const float* Wq = (b == 0) ? Wq0 : (b == 1) ? Wq1 : Wq2;
    const float* Wk = (b == 0) ? Wk0 : (b == 1) ? Wk1 : Wk2;

    // linear lower-tri block index -> (bi, bj), bi >= bj, 10x10 blocks
    int t = blockIdx.x;
    int bi = (int)((sqrtf(8.f * t + 1.f) - 1.f) * 0.5f);
    while ((bi + 1) * (bi + 2) / 2 <= t) bi++;
    while (bi * (bi + 1) / 2 > t) bi--;
    int bj = t - bi * (bi + 1) / 2;
    int i0 = bi * 32, j0 = bj * 32;

    __shared__ float sqI[32][17], skJ[32][17], sqJ[32][17], skI[32][17];
    int tx = threadIdx.x, ty = threadIdx.y;
    int tid = ty * 16 + tx;

    float aij[2][2] = {{0.f,0.f},{0.f,0.f}};
    float aji[2][2] = {{0.f,0.f},{0.f,0.f}};

    for (int o0 = 0; o0 < 300; o0 += 16) {
        #pragma unroll
        for (int e = 0; e < 2; e++) {
            int idx = e * 256 + tid;
            int r = idx >> 4, c = idx & 15;
            int o = o0 + c;
            bool ok = (o < 300);
            sqI[r][c] = (ok && i0 + r < 300) ? Wq[(i0 + r) * 300 + o] : 0.f;
            skI[r][c] = (ok && i0 + r < 300) ? Wk[(i0 + r) * 300 + o] : 0.f;
            sqJ[r][c] = (ok && j0 + r < 300) ? Wq[(j0 + r) * 300 + o] : 0.f;
            skJ[r][c] = (ok && j0 + r < 300) ? Wk[(j0 + r) * 300 + o] : 0.f;
        }
        __syncthreads();
        #pragma unroll
        for (int o = 0; o < 16; o++) {
            float qi0 = sqI[2*ty][o],   qi1 = sqI[2*ty+1][o];
            float ki0 = skI[2*ty][o],   ki1 = skI[2*ty+1][o];
            float qj0 = sqJ[2*tx][o],   qj1 = sqJ[2*tx+1][o];
            float kj0 = skJ[2*tx][o],   kj1 = skJ[2*tx+1][o];
            aij[0][0] += qi0 * kj0; aij[0][1] += qi0 * kj1;
            aij[1][0] += qi1 * kj0; aij[1][1] += qi1 * kj1;
            aji[0][0] += qj0 * ki0; aji[0][1] += qj1 * ki0;
            aji[1][0] += qj0 * ki1; aji[1][1] += qj1 * ki1;
        }
        __syncthreads();
    }

    __half* As = g_As + (size_t)b * NP * NP;
    #pragma unroll
    for (int r = 0; r < 2; r++)
        #pragma unroll
        for (int c = 0; c < 2; c++) {
            int i = i0 + 2 * ty + r, j = j0 + 2 * tx + c;
            if (i < 300 && j < 300) {
                if (i > j)       As[i * NP + j] = __float2half_rn(aij[r][c] + aji[r][c]);
                else if (i == j) As[i * NP + j] = __float2half_rn(aij[r][c]);
            }
        }
}

// ---- u_i = Wq[i].bk + Wk[i].bq -> As row 300;  block i==300: c = bq.bk ----
__global__ void k_u(const float* __restrict__ Wq0, const float* __restrict__ Wk0,
                    const float* __restrict__ bq0, const float* __restrict__ bk0,
                    const float* __restrict__ Wq1, const float* __restrict__ Wk1,
                    const float* __restrict__ bq1, const float* __restrict__ bk1,
                    const float* __restrict__ Wq2, const float* __restrict__ Wk2,
                    const float* __restrict__ bq2, const float* __restrict__ bk2) {
    int b = blockIdx.y;
    const float* Wq = (b == 0) ? Wq0 : (b == 1) ? Wq1 : Wq2;
    const float* Wk = (b == 0) ? Wk0 : (b == 1) ? Wk1 : Wk2;
    const float* bq = (b == 0) ? bq0 : (b == 1) ? bq1 : bq2;
    const float* bk = (b == 0) ? bk0 : (b == 1) ? bk1 : bk2;
    __shared__ float red[2];
    int i = blockIdx.x, tid = threadIdx.x;
    float s = 0.f;
    if (i < 300) { for (int o = tid; o < 300; o += 64) s += Wq[i*300+o]*bk[o] + Wk[i*300+o]*bq[o]; }
    else         { for (int o = tid; o < 300; o += 64) s += bq[o]*bk[o]; }
    #pragma unroll
    for (int o = 16; o; o >>= 1) s += __shfl_xor_sync(0xffffffffu, s, o);
    if ((tid & 31) == 0) red[tid >> 5] = s;
    __syncthreads();
    if (tid == 0) {
        float tot = red[0] + red[1];
        if (i < 300) g_As[(size_t)b * NP * NP + 300 * NP + i] = __float2half_rn(tot);
        else         g_C[b] = tot;
    }
}

// ---- merged projection: all 3 segments (T | CD | IM) in one launch ----
// seg = by>>10: 0=T (writes exact fp32 oT), 1=CD, 2=IM.
__global__ void __launch_bounds__(256, 2) k_proj(
    const float* __restrict__ Tf, const float* __restrict__ CDf,
    const float* __restrict__ IMf,
    const float* __restrict__ bt, const float* __restrict__ bim,
    float* __restrict__ outT)
{
    extern __shared__ __half sh[];
    __half* sA0 = sh;
    __half* sA1 = sh + PBM * SA_STR;
    __half* sB0 = sh + 2 * PBM * SA_STR;
    __half* sB1 = sB0 + PBK * SB_STR;

    int by = blockIdx.y;
    int seg = by >> 10;
    int m0 = (by & 1023) * PBM;
    const float* X = (seg == 0) ? Tf : (seg == 1) ? CDf : IMf;
    int K = (seg == 2) ? 2048 : 768;
    const __half* W = (seg == 2) ? g_Wim : g_Wt;
    const float* bias = (seg == 2) ? bim : bt;
    int ph = (seg == 0) ? 0 : (seg == 1) ? 2 : 1;

    int tid = threadIdx.x, wid = tid >> 5, lane = tid & 31;
    int wm = (wid >> 2) * 32, wn = (wid & 3) * 80;
    const float* Xb = X + (size_t)m0 * K;

    float acc[2][10][4];
    #pragma unroll
    for (int i = 0; i < 2; i++)
        #pragma unroll
        for (int f = 0; f < 10; f++)
            #pragma unroll
            for (int v = 0; v < 4; v++) acc[i][f][v] = 0.f;

    float4 xr[4];
    auto ldX = [&](int k0) {
        #pragma unroll
        for (int i = 0; i < 4; i++) {
            int idx = i * 256 + tid;           // 1024 float4 = 64 rows x 16
            int r = idx >> 4, c4 = idx & 15;
            xr[i] = *(const float4*)(Xb + (size_t)r * K + k0 + c4 * 4);
        }
    };
    auto stX = [&](__half* sA) {
        #pragma unroll
        for (int i = 0; i < 4; i++) {
            int idx = i * 256 + tid;
            int r = idx >> 4, c4 = idx & 15;
            __half2* d = (__half2*)(sA + r * SA_STR + c4 * 4);
            d[0] = __floats2half2_rn(xr[i].x, xr[i].y);
            d[1] = __floats2half2_rn(xr[i].z, xr[i].w);
        }
    };
    auto ldW = [&](__half* sB, int k0) {
        #pragma unroll
        for (int i = 0; i < 10; i++) {
            int idx = i * 256 + tid;           // 2560 int4 = 64 rows x 40
            int r = idx / 40, c = idx - r * 40;
            cp16(sB + r * SB_STR + c * 8, W + (size_t)(k0 + r) * NP + c * 8);
        }
    };

    ldX(0);
    ldW(sB0, 0); cpcommit();
    stX(sA0);
    cpwait0();
    __syncthreads();

    int nc = K >> 6;
    for (int c = 0; c < nc; c++) {
        __half* sAc = (c & 1) ? sA1 : sA0;
        __half* sBc = (c & 1) ? sB1 : sB0;
        __half* sAn = (c & 1) ? sA0 : sA1;
        __half* sBn = (c & 1) ? sB0 : sB1;
        bool more = (c + 1 < nc);
        if (more) { ldX((c + 1) * PBK); ldW(sBn, (c + 1) * PBK); cpcommit(); }
        #pragma unroll
        for (int kk = 0; kk < PBK; kk += 16) {
            uint32_t af[2][4];
            #pragma unroll
            for (int i = 0; i < 2; i++)
                ldsm4(af[i], su32(sAc + (wm + i*16 + (lane & 15)) * SA_STR + kk + ((lane >> 4) << 3)));
            #pragma unroll
            for (int j = 0; j < 5; j++) {
                uint32_t bf[4];
                ldsm4t(bf, su32(sBc + (kk + (lane & 15)) * SB_STR + wn + j*16 + ((lane >> 4) << 3)));
                #pragma unroll
                for (int i = 0; i < 2; i++) {
                    mma16816(acc[i][2*j],   af[i], bf);
                    mma16816(acc[i][2*j+1], af[i], bf + 2);
                }
            }
        }
        if (more) stX(sAn);
        cpwait0();
        __syncthreads();
    }

    int row = lane >> 2, colb = (lane & 3) * 2;
    __half* Ph = g_Ph[ph];
    #pragma unroll
    for (int i = 0; i < 2; i++)
        #pragma unroll
        for (int f = 0; f < 10; f++) {
            int cg = wn + f * 8 + colb;
            float b0 = (cg     < 300) ? bias[cg]     : 0.f;
            float b1 = (cg + 1 < 300) ? bias[cg + 1] : 0.f;
            #pragma unroll
            for (int h = 0; h < 2; h++) {
                int r = m0 + wm + i * 16 + row + h * 8;
                float v0 = acc[i][f][h*2]   + b0;
                float v1 = acc[i][f][h*2+1] + b1;
                *(__half2*)(Ph + (size_t)r * NP + cg) = __floats2half2_rn(v0, v1);
                if (seg == 0) {
                    if (cg     < 300) outT[(size_t)r * 300 + cg]     = v0;
                    if (cg + 1 < 300) outT[(size_t)r * 300 + cg + 1] = v1;
                }
            }
        }
}

// ---- fused attention (R11 config): 128-row tile, double-buffered triangular A,
//      u in As row 300 via p_hat[300]=1, softmax, scaled outputs ----
__global__ void __launch_bounds__(256) k_attn(float* __restrict__ out) {
    extern __shared__ __half sm[];
    __half* sP  = sm;                               // 128 x SP_STR
    __half* sAb[2] = { sm + 128 * SP_STR, sm + 128 * SP_STR + NP * AA_STR };
    float*  sAl = (float*)(sm + 128 * SP_STR + 2 * NP * AA_STR);  // [3][128]

    int tid = threadIdx.x, wid = tid >> 5, lane = tid & 31;
    int m0 = blockIdx.x * 128;
    int wm = wid * 16;
    int row = lane >> 2, colb = (lane & 3) * 2;

    auto stageP = [&](int b) {
        const __half* src = g_Ph[b] + (size_t)m0 * NP;
        #pragma unroll
        for (int i = 0; i < 20; i++) {
            int idx = i * 256 + tid;          // 5120 int4 = 128 rows x 40
            int r = idx / 40, c = idx - r * 40;
            cp16(sP + r * SP_STR + c * 8, src + (size_t)r * NP + c * 8);
        }
        cpcommit(); cpwait0();
        __syncthreads();
        if (tid < 128) sP[tid * SP_STR + 300] = __float2half_rn(1.f);   // p_hat[300]=1
        __syncthreads();
    };
    // stage s: branch b = s/5, col block nb = s%5; triangular: k rows [64*nb, 320)
    auto prefA = [&](int s, int buf) {
        int b = s / 5, nb = s - b * 5;
        int k0 = nb * 64;
        const __half* As = g_As + (size_t)b * NP * NP + nb * 64;
        __half* dst = sAb[buf];
        int total = (NP - k0) * 8;            // int4 transfers
        for (int idx = tid; idx < total; idx += 256) {
            int r = k0 + (idx >> 3), c = idx & 7;
            cp16(dst + r * AA_STR + c * 8, As + (size_t)r * NP + c * 8);
        }
        cpcommit();
    };

    float aLo = 0.f, aHi = 0.f;
    stageP(0);
    prefA(0, 0);

    for (int s = 0; s < 15; s++) {
        int b = s / 5, nb = s - b * 5;
        int k0 = nb * 64;
        if (nb == 0 && s > 0) {
            __syncthreads();
            stageP(b);
        }
        __syncthreads();
        if (s < 14) prefA(s + 1, (s + 1) & 1);
        if (s < 14) cpwait1(); else cpwait0();
        __syncthreads();

        const __half* Ab = sAb[s & 1];
        float accq[8][4];
        #pragma unroll
        for (int f = 0; f < 8; f++)
            #pragma unroll
            for (int v = 0; v < 4; v++) accq[f][v] = 0.f;
        for (int kk = k0; kk < NP; kk += 16) {
            uint32_t af[4];
            ldsm4(af, su32(sP + (wm + (lane & 15)) * SP_STR + kk + ((lane >> 4) << 3)));
            #pragma unroll
            for (int j = 0; j < 4; j++) {
                uint32_t bf[4];
                ldsm4t(bf, su32(Ab + (kk + (lane & 15)) * AA_STR + j*16 + ((lane >> 4) << 3)));
                mma16816(accq[2*j],   af, bf);
                mma16816(accq[2*j+1], af, bf + 2);
            }
        }
        int r0 = wm + row, r1 = wm + 8 + row;
        #pragma unroll
        for (int f = 0; f < 8; f++) {
            int c = nb * 64 + f * 8 + colb;
            float2 p0 = __half22float2(*(const __half2*)(sP + r0 * SP_STR + c));
            float2 p1 = __half22float2(*(const __half2*)(sP + r1 * SP_STR + c));
            aLo += accq[f][0] * p0.x + accq[f][1] * p0.y;
            aHi += accq[f][2] * p1.x + accq[f][3] * p1.y;
        }
        if (nb == 4) {
            aLo += __shfl_xor_sync(0xffffffffu, aLo, 1);
            aLo += __shfl_xor_sync(0xffffffffu, aLo, 2);
            aHi += __shfl_xor_sync(0xffffffffu, aHi, 1);
            aHi += __shfl_xor_sync(0xffffffffu, aHi, 2);
            if ((lane & 3) == 0) {
                sAl[b * 128 + r0] = aLo;
                sAl[b * 128 + r1] = aHi;
            }
            aLo = 0.f; aHi = 0.f;
        }
    }
    __syncthreads();

    if (tid < 128) {
        float is = rsqrtf(300.f);
        float aT = (sAl[tid]       + g_C[0]) * is;
        float aI = (sAl[128 + tid] + g_C[1]) * is;
        float aC = (sAl[256 + tid] + g_C[2]) * is;
        float zT = 1.f / (1.f + expf(-aT));
        float zI = 1.f / (1.f + expf(-aI));
        float zC = 1.f / (1.f + expf(-aC));
        float mI = zI * zT, mC = zC * zT;
        float mx = fmaxf(mI, mC);
        float e0 = expf(mI - mx), e1 = expf(mC - mx);
        float inv = 1.f / (e0 + e1);
        sAl[tid]       = e0 * inv;    // weight for IM
        sAl[128 + tid] = e1 * inv;    // weight for CD
    }
    __syncthreads();

    // outputs: oC from sP (holds CD tile), oI re-read from g_Ph[1]
    for (int r = wid; r < 128; r += 8) {
        float a0 = sAl[r], a1 = sAl[128 + r];
        const __half* pI = g_Ph[1] + (size_t)(m0 + r) * NP;
        float* oI = out + ((size_t)BATCH     + m0 + r) * 300;
        float* oC = out + ((size_t)2 * BATCH + m0 + r) * 300;
        for (int h = lane; h < 150; h += 32) {
            float2 fI = __half22float2(*(const __half2*)(pI + 2 * h));
            float2 fC = __half22float2(*(const __half2*)(sP + r * SP_STR + 2 * h));
            float2 vI; vI.x = a0 * fI.x; vI.y = a0 * fI.y;
            float2 vC; vC.x = a1 * fC.x; vC.y = a1 * fC.y;
            *(float2*)(oI + 2 * h) = vI;
            *(float2*)(oC + 2 * h) = vC;
        }
    }
}

extern "C" void kernel_launch(void* const* d_in, const int* in_sizes, int n_in,
                              void* d_out, int out_size) {
    const float* T   = (const float*)d_in[0];
    const float* IM  = (const float*)d_in[1];
    const float* CD  = (const float*)d_in[2];
    const float* Wt  = (const float*)d_in[3];
    const float* bt  = (const float*)d_in[4];
    const float* Wim = (const float*)d_in[5];
    const float* bim = (const float*)d_in[6];
    float* out = (float*)d_out;

    cudaFuncSetAttribute(k_proj, cudaFuncAttributeMaxDynamicSharedMemorySize, PROJ_SMEM);
    cudaFuncSetAttribute(k_attn, cudaFuncAttributeMaxDynamicSharedMemorySize, ATT_SMEM);

    k_convW<<<(768  * NP + 255) / 256, 256>>>(Wt,  0, 768);
    k_convW<<<(2048 * NP + 255) / 256, 256>>>(Wim, 1, 2048);

    // single merged proj launch: T | CD | IM
    k_proj<<<dim3(1, 3072), 256, PROJ_SMEM>>>(T, CD, IM, bt, bim, out);

    // fused symmetrized-A prep (55 lower-tri block pairs x 3 branches) + u/c
    k_prepAs<<<dim3(55, 1, 3), dim3(16, 16)>>>(
        (const float*)d_in[7],  (const float*)d_in[9],
        (const float*)d_in[11], (const float*)d_in[13],
        (const float*)d_in[15], (const float*)d_in[17]);
    k_u<<<dim3(301, 3), 64>>>(
        (const float*)d_in[7],  (const float*)d_in[9],  (const float*)d_in[8],  (const float*)d_in[10],
        (const float*)d_in[11], (const float*)d_in[13], (const float*)d_in[12], (const float*)d_in[14],
        (const float*)d_in[15], (const float*)d_in[17], (const float*)d_in[16], (const float*)d_in[18]);

    k_attn<<<BATCH / 128, 256, ATT_SMEM>>>(out);
}

// round 17
// speedup vs baseline: 1.0546x; 1.0546x over previous
#include <cuda_runtime.h>
#include <cuda_fp16.h>
#include <cstdint>

#define BATCH 65536
#define NP 320

// proj GEMM: BM=64, BN=320, BK=64, 256 threads, 2 CTAs/SM (M-split), split launches
#define PBM 64
#define PBK 64
#define SA_STR 72     // 64 + 8 pad (halves)
#define SB_STR 328    // 320 + 8 pad (halves)
#define PROJ_SMEM ((2*(PBM*SA_STR + PBK*SB_STR)) * 2)     // 102400 B

// attention kernel: 64-row P tile + single A buffer -> 2 CTAs/SM
#define SP_STR 328
#define AA_STR 72
#define ATT_SMEM ((64*SP_STR + NP*AA_STR) * 2 + 192*4)    // 88832 B

__device__ __align__(16) __half g_Wt [768  * NP];   // [K][NP]
__device__ __align__(16) __half g_Wim[2048 * NP];
__device__ __align__(16) __half g_As [3 * NP * NP];   // sym lower-tri + u in row 300 (rest 0)
__device__ float g_C[3];
__device__ __align__(16) __half g_Ph[3][(size_t)BATCH * NP];

static __device__ __forceinline__ uint32_t su32(const void* p) {
    return (uint32_t)__cvta_generic_to_shared(p);
}
static __device__ __forceinline__ void cp16(const __half* dst, const __half* src) {
    asm volatile("cp.async.cg.shared.global [%0], [%1], 16;\n" :: "r"(su32(dst)), "l"(src));
}
static __device__ __forceinline__ void cpcommit() { asm volatile("cp.async.commit_group;\n"); }
static __device__ __forceinline__ void cpwait0()  { asm volatile("cp.async.wait_group 0;\n" ::: "memory"); }
static __device__ __forceinline__ void ldsm4(uint32_t* r, uint32_t a) {
    asm volatile("ldmatrix.sync.aligned.m8n8.x4.shared.b16 {%0,%1,%2,%3}, [%4];\n"
                 : "=r"(r[0]), "=r"(r[1]), "=r"(r[2]), "=r"(r[3]) : "r"(a));
}
static __device__ __forceinline__ void ldsm4t(uint32_t* r, uint32_t a) {
    asm volatile("ldmatrix.sync.aligned.m8n8.x4.trans.shared.b16 {%0,%1,%2,%3}, [%4];\n"
                 : "=r"(r[0]), "=r"(r[1]), "=r"(r[2]), "=r"(r[3]) : "r"(a));
}
static __device__ __forceinline__ void mma16816(float* c, const uint32_t* a, const uint32_t* b) {
    asm volatile("mma.sync.aligned.m16n8k16.row.col.f32.f16.f16.f32 "
                 "{%0,%1,%2,%3}, {%4,%5,%6,%7}, {%8,%9}, {%0,%1,%2,%3};\n"
                 : "+f"(c[0]), "+f"(c[1]), "+f"(c[2]), "+f"(c[3])
                 : "r"(a[0]), "r"(a[1]), "r"(a[2]), "r"(a[3]), "r"(b[0]), "r"(b[1]));
}

// ---- convert weight [K x 300] fp32 -> [K x NP] fp16 (zero-padded) ----
__global__ void k_convW(const float* __restrict__ src, int which, int K) {
    __half* dst = which ? g_Wim : g_Wt;
    int i = blockIdx.x * 256 + threadIdx.x;
    if (i < K * NP) {
        int k = i / NP, n = i - k * NP;
        dst[i] = __float2half_rn(n < 300 ? src[k * 300 + n] : 0.f);
    }
}

// ---- fused symmetrized-triangular prep: lower-tri 32x32 block pair (bi>=bj) ----
__global__ void k_prepAs(const float* __restrict__ Wq0, const float* __restrict__ Wk0,
                         const float* __restrict__ Wq1, const float* __restrict__ Wk1,
                         const float* __restrict__ Wq2, const float* __restrict__ Wk2) {
    int b = blockIdx.z;
    const float* Wq = (b == 0) ? Wq0 : (b == 1) ? Wq1 : Wq2;
    const float* Wk = (b == 0) ? Wk0 : (b == 1) ? Wk1 : Wk2;

    int t = blockIdx.x;
    int bi = (int)((sqrtf(8.f * t + 1.f) - 1.f) * 0.5f);
    while ((bi + 1) * (bi + 2) / 2 <= t) bi++;
    while (bi * (bi + 1) / 2 > t) bi--;
    int bj = t - bi * (bi + 1) / 2;
    int i0 = bi * 32, j0 = bj * 32;

    __shared__ float sqI[32][17], skJ[32][17], sqJ[32][17], skI[32][17];
    int tx = threadIdx.x, ty = threadIdx.y;
    int tid = ty * 16 + tx;

    float aij[2][2] = {{0.f,0.f},{0.f,0.f}};
    float aji[2][2] = {{0.f,0.f},{0.f,0.f}};

    for (int o0 = 0; o0 < 300; o0 += 16) {
        #pragma unroll
        for (int e = 0; e < 2; e++) {
            int idx = e * 256 + tid;
            int r = idx >> 4, c = idx & 15;
            int o = o0 + c;
            bool ok = (o < 300);
            sqI[r][c] = (ok && i0 + r < 300) ? Wq[(i0 + r) * 300 + o] : 0.f;
            skI[r][c] = (ok && i0 + r < 300) ? Wk[(i0 + r) * 300 + o] : 0.f;
            sqJ[r][c] = (ok && j0 + r < 300) ? Wq[(j0 + r) * 300 + o] : 0.f;
            skJ[r][c] = (ok && j0 + r < 300) ? Wk[(j0 + r) * 300 + o] : 0.f;
        }
        __syncthreads();
        #pragma unroll
        for (int o = 0; o < 16; o++) {
            float qi0 = sqI[2*ty][o],   qi1 = sqI[2*ty+1][o];
            float ki0 = skI[2*ty][o],   ki1 = skI[2*ty+1][o];
            float qj0 = sqJ[2*tx][o],   qj1 = sqJ[2*tx+1][o];
            float kj0 = skJ[2*tx][o],   kj1 = skJ[2*tx+1][o];
            aij[0][0] += qi0 * kj0; aij[0][1] += qi0 * kj1;
            aij[1][0] += qi1 * kj0; aij[1][1] += qi1 * kj1;
            aji[0][0] += qj0 * ki0; aji[0][1] += qj1 * ki0;
            aji[1][0] += qj0 * ki1; aji[1][1] += qj1 * ki1;
        }
        __syncthreads();
    }

    __half* As = g_As + (size_t)b * NP * NP;
    #pragma unroll
    for (int r = 0; r < 2; r++)
        #pragma unroll
        for (int c = 0; c < 2; c++) {
            int i = i0 + 2 * ty + r, j = j0 + 2 * tx + c;
            if (i < 300 && j < 300) {
                if (i > j)       As[i * NP + j] = __float2half_rn(aij[r][c] + aji[r][c]);
                else if (i == j) As[i * NP + j] = __float2half_rn(aij[r][c]);
            }
        }
}

// ---- u_i = Wq[i].bk + Wk[i].bq -> As row 300;  block i==300: c = bq.bk ----
__global__ void k_u(const float* __restrict__ Wq0, const float* __restrict__ Wk0,
                    const float* __restrict__ bq0, const float* __restrict__ bk0,
                    const float* __restrict__ Wq1, const float* __restrict__ Wk1,
                    const float* __restrict__ bq1, const float* __restrict__ bk1,
                    const float* __restrict__ Wq2, const float* __restrict__ Wk2,
                    const float* __restrict__ bq2, const float* __restrict__ bk2) {
    int b = blockIdx.y;
    const float* Wq = (b == 0) ? Wq0 : (b == 1) ? Wq1 : Wq2;
    const float* Wk = (b == 0) ? Wk0 : (b == 1) ? Wk1 : Wk2;
    const float* bq = (b == 0) ? bq0 : (b == 1) ? bq1 : bq2;
    const float* bk = (b == 0) ? bk0 : (b == 1) ? bk1 : bk2;
    __shared__ float red[2];
    int i = blockIdx.x, tid = threadIdx.x;
    float s = 0.f;
    if (i < 300) { for (int o = tid; o < 300; o += 64) s += Wq[i*300+o]*bk[o] + Wk[i*300+o]*bq[o]; }
    else         { for (int o = tid; o < 300; o += 64) s += bq[o]*bk[o]; }
    #pragma unroll
    for (int o = 16; o; o >>= 1) s += __shfl_xor_sync(0xffffffffu, s, o);
    if ((tid & 31) == 0) red[tid >> 5] = s;
    __syncthreads();
    if (tid == 0) {
        float tot = red[0] + red[1];
        if (i < 300) g_As[(size_t)b * NP * NP + 300 * NP + i] = __float2half_rn(tot);
        else         g_C[b] = tot;
    }
}

// ---- projection (R11 config): Ph[ph] (fp16) = X @ W + bias; ph==0 writes fp32 oT ----
__global__ void __launch_bounds__(256, 2) k_proj(
    const float* __restrict__ X0, const float* __restrict__ X1,
    int K, int wsel, const float* __restrict__ bias,
    int ph0, int ph1, float* __restrict__ outT, int nsplit)
{
    extern __shared__ __half sh[];
    __half* sA0 = sh;
    __half* sA1 = sh + PBM * SA_STR;
    __half* sB0 = sh + 2 * PBM * SA_STR;
    __half* sB1 = sB0 + PBK * SB_STR;
    const __half* W = wsel ? g_Wim : g_Wt;

    int by = blockIdx.y;
    bool sel = (by >= nsplit);
    const float* X = sel ? X1 : X0;
    int ph = sel ? ph1 : ph0;
    int m0 = (sel ? by - nsplit : by) * PBM;

    int tid = threadIdx.x, wid = tid >> 5, lane = tid & 31;
    int wm = (wid >> 2) * 32, wn = (wid & 3) * 80;
    const float* Xb = X + (size_t)m0 * K;

    float acc[2][10][4];
    #pragma unroll
    for (int i = 0; i < 2; i++)
        #pragma unroll
        for (int f = 0; f < 10; f++)
            #pragma unroll
            for (int v = 0; v < 4; v++) acc[i][f][v] = 0.f;

    float4 xr[4];
    auto ldX = [&](int k0) {
        #pragma unroll
        for (int i = 0; i < 4; i++) {
            int idx = i * 256 + tid;           // 1024 float4 = 64 rows x 16
            int r = idx >> 4, c4 = idx & 15;
            xr[i] = *(const float4*)(Xb + (size_t)r * K + k0 + c4 * 4);
        }
    };
    auto stX = [&](__half* sA) {
        #pragma unroll
        for (int i = 0; i < 4; i++) {
            int idx = i * 256 + tid;
            int r = idx >> 4, c4 = idx & 15;
            __half2* d = (__half2*)(sA + r * SA_STR + c4 * 4);
            d[0] = __floats2half2_rn(xr[i].x, xr[i].y);
            d[1] = __floats2half2_rn(xr[i].z, xr[i].w);
        }
    };
    auto ldW = [&](__half* sB, int k0) {
        #pragma unroll
        for (int i = 0; i < 10; i++) {
            int idx = i * 256 + tid;           // 2560 int4 = 64 rows x 40
            int r = idx / 40, c = idx - r * 40;
            cp16(sB + r * SB_STR + c * 8, W + (size_t)(k0 + r) * NP + c * 8);
        }
    };

    ldX(0);
    ldW(sB0, 0); cpcommit();
    stX(sA0);
    cpwait0();
    __syncthreads();

    int nc = K >> 6;
    for (int c = 0; c < nc; c++) {
        __half* sAc = (c & 1) ? sA1 : sA0;
        __half* sBc = (c & 1) ? sB1 : sB0;
        __half* sAn = (c & 1) ? sA0 : sA1;
        __half* sBn = (c & 1) ? sB0 : sB1;
        bool more = (c + 1 < nc);
        if (more) { ldX((c + 1) * PBK); ldW(sBn, (c + 1) * PBK); cpcommit(); }
        #pragma unroll
        for (int kk = 0; kk < PBK; kk += 16) {
            uint32_t af[2][4];
            #pragma unroll
            for (int i = 0; i < 2; i++)
                ldsm4(af[i], su32(sAc + (wm + i*16 + (lane & 15)) * SA_STR + kk + ((lane >> 4) << 3)));
            #pragma unroll
            for (int j = 0; j < 5; j++) {
                uint32_t bf[4];
                ldsm4t(bf, su32(sBc + (kk + (lane & 15)) * SB_STR + wn + j*16 + ((lane >> 4) << 3)));
                #pragma unroll
                for (int i = 0; i < 2; i++) {
                    mma16816(acc[i][2*j],   af[i], bf);
                    mma16816(acc[i][2*j+1], af[i], bf + 2);
                }
            }
        }
        if (more) stX(sAn);
        cpwait0();
        __syncthreads();
    }

    int row = lane >> 2, colb = (lane & 3) * 2;
    __half* Ph = g_Ph[ph];
    #pragma unroll
    for (int i = 0; i < 2; i++)
        #pragma unroll
        for (int f = 0; f < 10; f++) {
            int cg = wn + f * 8 + colb;
            float b0 = (cg     < 300) ? bias[cg]     : 0.f;
            float b1 = (cg + 1 < 300) ? bias[cg + 1] : 0.f;
            #pragma unroll
            for (int h = 0; h < 2; h++) {
                int r = m0 + wm + i * 16 + row + h * 8;
                float v0 = acc[i][f][h*2]   + b0;
                float v1 = acc[i][f][h*2+1] + b1;
                *(__half2*)(Ph + (size_t)r * NP + cg) = __floats2half2_rn(v0, v1);
                if (ph == 0) {
                    if (cg     < 300) outT[(size_t)r * 300 + cg]     = v0;
                    if (cg + 1 < 300) outT[(size_t)r * 300 + cg + 1] = v1;
                }
            }
        }
}

// ---- fused attention (R15 config): 64-row tiles, 2 CTAs/SM; triangular quad forms,
//      u in As row 300, softmax, scaled outputs ----
__global__ void __launch_bounds__(256) k_attn(float* __restrict__ out) {
    extern __shared__ __half sm[];
    __half* sP  = sm;                              // 64 x SP_STR
    __half* sA  = sm + 64 * SP_STR;                // 320 x AA_STR (single buffer)
    float*  sAl = (float*)(sm + 64 * SP_STR + NP * AA_STR);  // [3][64]

    int tid = threadIdx.x, wid = tid >> 5, lane = tid & 31;
    int m0 = blockIdx.x * 64;
    int wm = (wid >> 1) * 16;       // 4 M-groups of 16 rows
    int wnl = (wid & 1) * 32;       // 2 N-halves of 32 cols
    int row = lane >> 2, colb = (lane & 3) * 2;

    for (int i = tid; i < 192; i += 256) sAl[i] = 0.f;
    __syncthreads();

    auto stageP = [&](int b) {
        const __half* src = g_Ph[b] + (size_t)m0 * NP;
        #pragma unroll
        for (int i = 0; i < 10; i++) {
            int idx = i * 256 + tid;          // 2560 int4 = 64 rows x 40
            int r = idx / 40, c = idx - r * 40;
            cp16(sP + r * SP_STR + c * 8, src + (size_t)r * NP + c * 8);
        }
        cpcommit(); cpwait0();
        __syncthreads();
        if (tid < 64) sP[tid * SP_STR + 300] = __float2half_rn(1.f);   // p_hat[300]=1
        __syncthreads();
    };

    float aLo = 0.f, aHi = 0.f;

    for (int s = 0; s < 15; s++) {
        int b = s / 5, nb = s - b * 5;
        int k0 = nb * 64;
        if (nb == 0) {
            __syncthreads();                   // prior reads of sP done
            stageP(b);
        }
        __syncthreads();                       // prior reads of sA done
        {   // load A tile (triangular k-range) into single buffer
            const __half* As = g_As + (size_t)b * NP * NP + nb * 64;
            int total = (NP - k0) * 8;         // int4 transfers
            for (int idx = tid; idx < total; idx += 256) {
                int r = k0 + (idx >> 3), c = idx & 7;
                cp16(sA + r * AA_STR + c * 8, As + (size_t)r * NP + c * 8);
            }
            cpcommit(); cpwait0();
            __syncthreads();
        }

        float accq[4][4];
        #pragma unroll
        for (int f = 0; f < 4; f++)
            #pragma unroll
            for (int v = 0; v < 4; v++) accq[f][v] = 0.f;
        for (int kk = k0; kk < NP; kk += 16) {
            uint32_t af[4];
            ldsm4(af, su32(sP + (wm + (lane & 15)) * SP_STR + kk + ((lane >> 4) << 3)));
            #pragma unroll
            for (int j = 0; j < 2; j++) {
                uint32_t bf[4];
                ldsm4t(bf, su32(sA + (kk + (lane & 15)) * AA_STR + wnl + j*16 + ((lane >> 4) << 3)));
                mma16816(accq[2*j],   af, bf);
                mma16816(accq[2*j+1], af, bf + 2);
            }
        }
        int r0 = wm + row, r1 = wm + 8 + row;
        #pragma unroll
        for (int f = 0; f < 4; f++) {
            int c = nb * 64 + wnl + f * 8 + colb;
            float2 p0 = __half22float2(*(const __half2*)(sP + r0 * SP_STR + c));
            float2 p1 = __half22float2(*(const __half2*)(sP + r1 * SP_STR + c));
            aLo += accq[f][0] * p0.x + accq[f][1] * p0.y;
            aHi += accq[f][2] * p1.x + accq[f][3] * p1.y;
        }
        if (nb == 4) {
            aLo += __shfl_xor_sync(0xffffffffu, aLo, 1);
            aLo += __shfl_xor_sync(0xffffffffu, aLo, 2);
            aHi += __shfl_xor_sync(0xffffffffu, aHi, 1);
            aHi += __shfl_xor_sync(0xffffffffu, aHi, 2);
            if ((lane & 3) == 0) {
                atomicAdd(&sAl[b * 64 + r0], aLo);   // two N-half warps share a slot
                atomicAdd(&sAl[b * 64 + r1], aHi);
            }
            aLo = 0.f; aHi = 0.f;
        }
    }
    __syncthreads();

    if (tid < 64) {
        float is = rsqrtf(300.f);
        float aT = (sAl[tid]       + g_C[0]) * is;
        float aI = (sAl[64  + tid] + g_C[1]) * is;
        float aC = (sAl[128 + tid] + g_C[2]) * is;
        float zT = 1.f / (1.f + expf(-aT));
        float zI = 1.f / (1.f + expf(-aI));
        float zC = 1.f / (1.f + expf(-aC));
        float mI = zI * zT, mC = zC * zT;
        float mx = fmaxf(mI, mC);
        float e0 = expf(mI - mx), e1 = expf(mC - mx);
        float inv = 1.f / (e0 + e1);
        sAl[tid]      = e0 * inv;     // weight for IM
        sAl[64 + tid] = e1 * inv;     // weight for CD
    }
    __syncthreads();

    // outputs: oC from sP (holds CD tile), oI re-read from g_Ph[1]
    for (int r = wid; r < 64; r += 8) {
        float a0 = sAl[r], a1 = sAl[64 + r];
        const __half* pI = g_Ph[1] + (size_t)(m0 + r) * NP;
        float* oI = out + ((size_t)BATCH     + m0 + r) * 300;
        float* oC = out + ((size_t)2 * BATCH + m0 + r) * 300;
        for (int h = lane; h < 150; h += 32) {
            float2 fI = __half22float2(*(const __half2*)(pI + 2 * h));
            float2 fC = __half22float2(*(const __half2*)(sP + r * SP_STR + 2 * h));
            float2 vI; vI.x = a0 * fI.x; vI.y = a0 * fI.y;
            float2 vC; vC.x = a1 * fC.x; vC.y = a1 * fC.y;
            *(float2*)(oI + 2 * h) = vI;
            *(float2*)(oC + 2 * h) = vC;
        }
    }
}

extern "C" void kernel_launch(void* const* d_in, const int* in_sizes, int n_in,
                              void* d_out, int out_size) {
    const float* T   = (const float*)d_in[0];
    const float* IM  = (const float*)d_in[1];
    const float* CD  = (const float*)d_in[2];
    const float* Wt  = (const float*)d_in[3];
    const float* bt  = (const float*)d_in[4];
    const float* Wim = (const float*)d_in[5];
    const float* bim = (const float*)d_in[6];
    float* out = (float*)d_out;

    cudaFuncSetAttribute(k_proj, cudaFuncAttributeMaxDynamicSharedMemorySize, PROJ_SMEM);
    cudaFuncSetAttribute(k_attn, cudaFuncAttributeMaxDynamicSharedMemorySize, ATT_SMEM);

    k_convW<<<(768  * NP + 255) / 256, 256>>>(Wt,  0, 768);
    k_convW<<<(2048 * NP + 255) / 256, 256>>>(Wim, 1, 2048);

    // split proj launches (uniform block duration per launch)
    k_proj<<<dim3(1, 2048), 256, PROJ_SMEM>>>(T, CD, 768, 0, bt, 0, 2, out, 1024);
    k_proj<<<dim3(1, 1024), 256, PROJ_SMEM>>>(IM, IM, 2048, 1, bim, 1, 1, nullptr, 1024);

    // fused symmetrized-A prep (55 lower-tri block pairs x 3 branches) + u/c
    k_prepAs<<<dim3(55, 1, 3), dim3(16, 16)>>>(
        (const float*)d_in[7],  (const float*)d_in[9],
        (const float*)d_in[11], (const float*)d_in[13],
        (const float*)d_in[15], (const float*)d_in[17]);
    k_u<<<dim3(301, 3), 64>>>(
        (const float*)d_in[7],  (const float*)d_in[9],  (const float*)d_in[8],  (const float*)d_in[10],
        (const float*)d_in[11], (const float*)d_in[13], (const float*)d_in[12], (const float*)d_in[14],
        (const float*)d_in[15], (const float*)d_in[17], (const float*)d_in[16], (const float*)d_in[18]);

    k_attn<<<BATCH / 64, 256, ATT_SMEM>>>(out);
}